// round 3
// baseline (speedup 1.0000x reference)
#include <cuda_runtime.h>
#include <cstdint>

// RWKV7 WKV scan, latency-optimized.
//   P_t = S_{t-1} (.) w_t + v_t k_t^T          (elementwise, no sa dependence)
//   S_t = P_t + sa_t * b_t                     (sa_t = S_{t-1} . a_t, scalar/row)
//   sa_{t+1} = (P_t . a_{t+1}) + sa_t * (b_t . a_{t+1})   <-- 1 FMA + reduce
//   y_t = S_t . r_t                            (reduced one step deferred)
//
// 2048 independent row-scans. Grid 128 CTAs (32 heads x 4 row-parts of 16),
// block 128. 8 lanes per row; each thread owns 8 key-columns held as 4
// packed f32x2 (u64) registers. No SMEM, no barriers: each warp streams its
// step vectors from global into registers with prefetch distance 2.
// All elementwise math uses fma.rn.f32x2 / mul.rn.f32x2 (sm_103a packed fp32).

#define HH 32
#define NN 64
#define STEP (HH * NN)   // 2048 floats per timestep

typedef unsigned long long u64;

__device__ __forceinline__ u64 fma2(u64 a, u64 b, u64 c) {
    u64 d; asm("fma.rn.f32x2 %0, %1, %2, %3;" : "=l"(d) : "l"(a), "l"(b), "l"(c)); return d;
}
__device__ __forceinline__ u64 mul2(u64 a, u64 b) {
    u64 d; asm("mul.rn.f32x2 %0, %1, %2;" : "=l"(d) : "l"(a), "l"(b)); return d;
}
__device__ __forceinline__ u64 pack2(float lo, float hi) {
    u64 d; asm("mov.b64 %0, {%1, %2};" : "=l"(d) : "f"(lo), "f"(hi)); return d;
}
__device__ __forceinline__ float hsum2(u64 a) {
    float x, y; asm("mov.b64 {%0, %1}, %2;" : "=f"(x), "=f"(y) : "l"(a)); return x + y;
}
// load 8 consecutive floats (16B-aligned) as 4 packed f32x2
__device__ __forceinline__ void ld4(u64 o[4], const float* p) {
    ulonglong2 x = *reinterpret_cast<const ulonglong2*>(p);
    ulonglong2 y = *reinterpret_cast<const ulonglong2*>(p + 4);
    o[0] = x.x; o[1] = x.y; o[2] = y.x; o[3] = y.y;
}

__global__ __launch_bounds__(128, 1)
void wkv7_scan_kernel(const float* __restrict__ rP, const float* __restrict__ wP,
                      const float* __restrict__ kP, const float* __restrict__ vP,
                      const float* __restrict__ aP, const float* __restrict__ bP,
                      const float* __restrict__ stateP,
                      float* __restrict__ yOut, float* __restrict__ sOut,
                      int T)
{
    const int tid  = threadIdx.x;
    const int h    = blockIdx.x >> 2;
    const int part = blockIdx.x & 3;
    const int iloc = tid >> 3;
    const int q    = tid & 7;
    const int i    = part * 16 + iloc;   // row (value dim)
    const int j0   = q * 8;              // first key-col owned

    const int vecBase = h * NN + j0;

    // ---- state rows (packed) ----
    u64 s2[4];
    ld4(s2, stateP + ((size_t)h * NN + i) * NN + j0);

    const float* wPtr = wP + vecBase;
    const float* kPtr = kP + vecBase;
    const float* bPtr = bP + vecBase;
    const float* rPtr = rP + vecBase;
    const float* aPtr = aP + vecBase;        // consumed at t for a_{t+1}
    const float* vPtr = vP + h * NN + i;     // scalar stream
    float*       yPtr = yOut + (size_t)h * NN + i;

    // ---- prologue: sa_0 = state . a_0 ----
    float sa;
    {
        u64 a0[4]; ld4(a0, aPtr);
        u64 acc = mul2(s2[0], a0[0]);
        acc = fma2(s2[1], a0[1], acc);
        acc = fma2(s2[2], a0[2], acc);
        acc = fma2(s2[3], a0[3], acc);
        sa = hsum2(acc);
        sa += __shfl_xor_sync(0xffffffffu, sa, 1);
        sa += __shfl_xor_sync(0xffffffffu, sa, 2);
        sa += __shfl_xor_sync(0xffffffffu, sa, 4);
    }

    // ---- preload register sets for iter 0 and 1 ----
    // set t holds: (w,k,b,r)_t slices, vi_t, a_{t+1} slice
    u64 wv[2][4], kv[2][4], bv[2][4], rv[2][4], av[2][4];
    float vi[2];
    #pragma unroll
    for (int p = 0; p < 2; ++p) {
        ld4(wv[p], wPtr + (size_t)p * STEP);
        ld4(kv[p], kPtr + (size_t)p * STEP);
        ld4(bv[p], bPtr + (size_t)p * STEP);
        ld4(rv[p], rPtr + (size_t)p * STEP);
        const int ap = (p + 1 < T) ? (p + 1) : (T - 1);
        ld4(av[p], aPtr + (size_t)ap * STEP);
        vi[p] = vPtr[(size_t)p * STEP];
    }

    u64 py2 = 0;   // packed y partials from previous step (0.0f,0.0f)

    #pragma unroll 2
    for (int t = 0; t < T; ++t) {
        const int c = t & 1;

        const u64 vi2 = pack2(vi[c], vi[c]);
        // P = s (.) w + vi * k     (independent of sa)
        const u64 P0 = fma2(s2[0], wv[c][0], mul2(vi2, kv[c][0]));
        const u64 P1 = fma2(s2[1], wv[c][1], mul2(vi2, kv[c][1]));
        const u64 P2 = fma2(s2[2], wv[c][2], mul2(vi2, kv[c][2]));
        const u64 P3 = fma2(s2[3], wv[c][3], mul2(vi2, kv[c][3]));

        // dPA = P . a_{t+1},  dBA = b . a_{t+1}   (both independent of sa)
        u64 accP = mul2(P0, av[c][0]);
        u64 accB = mul2(bv[c][0], av[c][0]);
        accP = fma2(P1, av[c][1], accP);
        accB = fma2(bv[c][1], av[c][1], accB);
        accP = fma2(P2, av[c][2], accP);
        accB = fma2(bv[c][2], av[c][2], accB);
        accP = fma2(P3, av[c][3], accP);
        accB = fma2(bv[c][3], av[c][3], accB);
        const float dPA = hsum2(accP);
        const float dBA = hsum2(accB);
        float yv = hsum2(py2);            // y partial of step t-1

        // ---- the only serial op: next-sa partial ----
        float d = fmaf(sa, dBA, dPA);
        // interleaved 8-lane reduces: d (critical) and yv (deferred)
        d  += __shfl_xor_sync(0xffffffffu, d, 1);
        yv += __shfl_xor_sync(0xffffffffu, yv, 1);
        d  += __shfl_xor_sync(0xffffffffu, d, 2);
        yv += __shfl_xor_sync(0xffffffffu, yv, 2);
        d  += __shfl_xor_sync(0xffffffffu, d, 4);
        yv += __shfl_xor_sync(0xffffffffu, yv, 4);

        if (t > 0 && q == 0) yPtr[(size_t)(t - 1) * STEP] = yv;

        // ---- state update S_t = P + sa * b (off critical path) ----
        const u64 sa2 = pack2(sa, sa);
        s2[0] = fma2(sa2, bv[c][0], P0);
        s2[1] = fma2(sa2, bv[c][1], P1);
        s2[2] = fma2(sa2, bv[c][2], P2);
        s2[3] = fma2(sa2, bv[c][3], P3);

        // y partials for step t (reduced next iteration)
        u64 acc = mul2(s2[0], rv[c][0]);
        acc = fma2(s2[1], rv[c][1], acc);
        acc = fma2(s2[2], rv[c][2], acc);
        acc = fma2(s2[3], rv[c][3], acc);
        py2 = acc;

        sa = d;

        // ---- prefetch set t+2 into slot c (just consumed) ----
        {
            const int tf = (t + 2 < T) ? (t + 2) : (T - 1);        // clamp: values unused if clamped
            const int ta = (t + 3 < T) ? (t + 3) : (T - 1);
            const size_t off = (size_t)tf * STEP;
            ld4(wv[c], wPtr + off);
            ld4(kv[c], kPtr + off);
            ld4(bv[c], bPtr + off);
            ld4(rv[c], rPtr + off);
            ld4(av[c], aPtr + (size_t)ta * STEP);
            vi[c] = vPtr[off];
        }
    }

    // ---- epilogue: y for t = T-1 ----
    {
        float yv = hsum2(py2);
        yv += __shfl_xor_sync(0xffffffffu, yv, 1);
        yv += __shfl_xor_sync(0xffffffffu, yv, 2);
        yv += __shfl_xor_sync(0xffffffffu, yv, 4);
        if (q == 0) yPtr[(size_t)(T - 1) * STEP] = yv;
    }

    // ---- final state ----
    {
        float* op = sOut + ((size_t)h * NN + i) * NN + j0;
        ulonglong2 lo, hi;
        lo.x = s2[0]; lo.y = s2[1];
        hi.x = s2[2]; hi.y = s2[3];
        *reinterpret_cast<ulonglong2*>(op)     = lo;
        *reinterpret_cast<ulonglong2*>(op + 4) = hi;
    }
}

extern "C" void kernel_launch(void* const* d_in, const int* in_sizes, int n_in,
                              void* d_out, int out_size)
{
    const float* r  = (const float*)d_in[0];
    const float* w  = (const float*)d_in[1];
    const float* k  = (const float*)d_in[2];
    const float* v  = (const float*)d_in[3];
    const float* a  = (const float*)d_in[4];
    const float* b  = (const float*)d_in[5];
    const float* st = (const float*)d_in[6];

    const int T = in_sizes[0] / (HH * NN);

    float* y    = (float*)d_out;
    float* sfin = y + (size_t)T * HH * NN;

    wkv7_scan_kernel<<<HH * 4, 128>>>(r, w, k, v, a, b, st, y, sfin, T);
}

// round 4
// speedup vs baseline: 1.4875x; 1.4875x over previous
#include <cuda_runtime.h>
#include <cstdint>

// RWKV7 WKV scan — latency-optimized (v4).
//   P_t = S_{t-1} (.) w_t + v_t k_t^T            (independent of sa)
//   S_t = P_t + sa_t * b_t
//   sa_{t+1} = (P_t . a_{t+1}) + sa_t * (b_t . a_{t+1})   <- 1 FMA + 8-lane reduce
//   y_t = S_t . r_t                              (reduced one step deferred)
//
// 2048 independent row-scans. Grid 512 CTAs (32 heads x 16 slices of 4 rows),
// block 32 (one warp): __syncthreads costs ~3 cyc, no inter-warp lockstep.
// Per-step head vectors (a,w,b,k,r,v : 6x64 f32 = 1.5KB) flow through an
// 8-stage cp.async SMEM pipeline (prologue depth 6, wait_group 3) so stages
// t..t+3 are always resident; register sets are double-buffered from SMEM one
// iteration ahead, so neither LDG nor LDS latency touches the recurrence.
// Elementwise math uses packed fma.rn.f32x2.

#define HH 32
#define NN 64
#define STEP (HH * NN)   // 2048 floats per timestep
#define NBUF 8
#define STAGE_FLOATS 384 // 6 * 64

typedef unsigned long long u64;

__device__ __forceinline__ u64 fma2(u64 a, u64 b, u64 c) {
    u64 d; asm("fma.rn.f32x2 %0, %1, %2, %3;" : "=l"(d) : "l"(a), "l"(b), "l"(c)); return d;
}
__device__ __forceinline__ u64 mul2(u64 a, u64 b) {
    u64 d; asm("mul.rn.f32x2 %0, %1, %2;" : "=l"(d) : "l"(a), "l"(b)); return d;
}
__device__ __forceinline__ u64 pack2(float lo, float hi) {
    u64 d; asm("mov.b64 %0, {%1, %2};" : "=l"(d) : "f"(lo), "f"(hi)); return d;
}
__device__ __forceinline__ float hsum2(u64 a) {
    float x, y; asm("mov.b64 {%0, %1}, %2;" : "=f"(x), "=f"(y) : "l"(a)); return x + y;
}
// 8 consecutive floats (16B aligned) as 4 packed f32x2
__device__ __forceinline__ void ld4(u64 o[4], const float* p) {
    ulonglong2 x = *reinterpret_cast<const ulonglong2*>(p);
    ulonglong2 y = *reinterpret_cast<const ulonglong2*>(p + 4);
    o[0] = x.x; o[1] = x.y; o[2] = y.x; o[3] = y.y;
}

__device__ __forceinline__ void cp_async16(void* smem_dst, const void* gsrc) {
    unsigned saddr = (unsigned)__cvta_generic_to_shared(smem_dst);
    asm volatile("cp.async.ca.shared.global [%0], [%1], 16;\n"
                 :: "r"(saddr), "l"(gsrc) : "memory");
}

__global__ __launch_bounds__(32, 1)
void wkv7_scan_kernel(const float* __restrict__ rP, const float* __restrict__ wP,
                      const float* __restrict__ kP, const float* __restrict__ vP,
                      const float* __restrict__ aP, const float* __restrict__ bP,
                      const float* __restrict__ stateP,
                      float* __restrict__ yOut, float* __restrict__ sOut,
                      int T)
{
    __shared__ __align__(16) float sbuf[NBUF][STAGE_FLOATS];

    const int tid   = threadIdx.x;
    const int h     = blockIdx.x >> 4;
    const int slice = blockIdx.x & 15;
    const int iloc  = tid >> 3;
    const int q     = tid & 7;
    const int i     = slice * 4 + iloc;   // row (value dim)
    const int j0    = q * 8;              // first owned key-col

    // ---- cp.async loader: each thread copies 3 float4 per stage ----
    // stage layout (floats): a(0), w(64), b(128), k(192), r(256), v(320)
    const float* srcs[6] = { aP, wP, bP, kP, rP, vP };
    const int f0 = tid, f1 = tid + 32, f2 = tid + 64;
    const float* g0 = srcs[f0 >> 4] + h * NN + (f0 & 15) * 4;
    const float* g1 = srcs[f1 >> 4] + h * NN + (f1 & 15) * 4;
    const float* g2 = srcs[f2 >> 4] + h * NN + (f2 & 15) * 4;
    const int o0 = f0 * 4, o1 = f1 * 4, o2 = f2 * 4;

    auto issueStage = [&](int slot, int step) {
        float* d = sbuf[slot];
        const size_t off = (size_t)step * STEP;
        cp_async16(d + o0, g0 + off);
        cp_async16(d + o1, g1 + off);
        cp_async16(d + o2, g2 + off);
        asm volatile("cp.async.commit_group;\n" ::: "memory");
    };

    // ---- prologue: commit stages 0..5 ----
    #pragma unroll
    for (int p = 0; p < 6; ++p)
        issueStage(p, (p < T) ? p : (T - 1));

    // ---- state rows (packed) ----
    u64 s2[4];
    ld4(s2, stateP + ((size_t)h * NN + i) * NN + j0);

    asm volatile("cp.async.wait_group 3;\n" ::: "memory");   // stages 0..2 ready
    __syncthreads();

    // ---- double-buffered register sets; set c used at iter t (c = t&1) ----
    u64 wv[2][4], kv[2][4], bv[2][4], rv[2][4], av[2][4];
    float vi[2];
    {
        const float* B0 = sbuf[0];
        const float* B1 = sbuf[(1 < T) ? 1 : 0];
        ld4(wv[0], B0 +  64 + j0);
        ld4(bv[0], B0 + 128 + j0);
        ld4(kv[0], B0 + 192 + j0);
        ld4(rv[0], B0 + 256 + j0);
        vi[0] = B0[320 + i];
        ld4(av[0], B1 + j0);                 // a_1 slice
    }

    // ---- sa_0 = state . a_0 ----
    float sa;
    {
        u64 a0[4]; ld4(a0, sbuf[0] + j0);
        u64 acc = mul2(s2[0], a0[0]);
        acc = fma2(s2[1], a0[1], acc);
        acc = fma2(s2[2], a0[2], acc);
        acc = fma2(s2[3], a0[3], acc);
        sa = hsum2(acc);
        sa += __shfl_xor_sync(0xffffffffu, sa, 1);
        sa += __shfl_xor_sync(0xffffffffu, sa, 2);
        sa += __shfl_xor_sync(0xffffffffu, sa, 4);
    }

    float* yPtr = yOut + (size_t)h * NN + i;
    u64 py2 = 0;   // packed y partials of previous step

    #pragma unroll 2
    for (int t = 0; t < T; ++t) {
        const int c = t & 1, n = c ^ 1;

        // fire cp.async for stage t+6 (slot distinct from all reads this iter)
        issueStage((t + 6) & 7, (t + 6 < T) ? (t + 6) : (T - 1));

        // ---- P = s(.)w + vi*k   (no sa dependence) ----
        const u64 vi2 = pack2(vi[c], vi[c]);
        const u64 P0 = fma2(s2[0], wv[c][0], mul2(vi2, kv[c][0]));
        const u64 P1 = fma2(s2[1], wv[c][1], mul2(vi2, kv[c][1]));
        const u64 P2 = fma2(s2[2], wv[c][2], mul2(vi2, kv[c][2]));
        const u64 P3 = fma2(s2[3], wv[c][3], mul2(vi2, kv[c][3]));

        // ---- dPA = P . a_{t+1},  dBA = b . a_{t+1} ----
        u64 accP = mul2(P0, av[c][0]);
        u64 accB = mul2(bv[c][0], av[c][0]);
        accP = fma2(P1, av[c][1], accP);
        accB = fma2(bv[c][1], av[c][1], accB);
        accP = fma2(P2, av[c][2], accP);
        accB = fma2(bv[c][2], av[c][2], accB);
        accP = fma2(P3, av[c][3], accP);
        accB = fma2(bv[c][3], av[c][3], accB);
        const float dPA = hsum2(accP);
        const float dBA = hsum2(accB);
        float yv = hsum2(py2);                    // y of step t-1

        // ---- serial op + interleaved 8-lane reduces ----
        float d = fmaf(sa, dBA, dPA);
        d  += __shfl_xor_sync(0xffffffffu, d, 1);
        yv += __shfl_xor_sync(0xffffffffu, yv, 1);
        d  += __shfl_xor_sync(0xffffffffu, d, 2);
        yv += __shfl_xor_sync(0xffffffffu, yv, 2);
        d  += __shfl_xor_sync(0xffffffffu, d, 4);
        yv += __shfl_xor_sync(0xffffffffu, yv, 4);

        if (t > 0 && q == 0) yPtr[(size_t)(t - 1) * STEP] = yv;

        // ---- S_t = P + sa*b ; y partials for step t ----
        const u64 sa2 = pack2(sa, sa);
        s2[0] = fma2(sa2, bv[c][0], P0);
        s2[1] = fma2(sa2, bv[c][1], P1);
        s2[2] = fma2(sa2, bv[c][2], P2);
        s2[3] = fma2(sa2, bv[c][3], P3);

        u64 acc = mul2(s2[0], rv[c][0]);
        acc = fma2(s2[1], rv[c][1], acc);
        acc = fma2(s2[2], rv[c][2], acc);
        acc = fma2(s2[3], rv[c][3], acc);
        py2 = acc;

        sa = d;

        // ---- stage t+1..t+3 now guaranteed; refill register set n ----
        asm volatile("cp.async.wait_group 3;\n" ::: "memory");
        __syncthreads();
        {
            const float* B1 = sbuf[(t + 1) & 7];  // step t+1 vectors
            const float* B2 = sbuf[(t + 2) & 7];  // a_{t+2}
            ld4(wv[n], B1 +  64 + j0);
            ld4(bv[n], B1 + 128 + j0);
            ld4(kv[n], B1 + 192 + j0);
            ld4(rv[n], B1 + 256 + j0);
            vi[n] = B1[320 + i];
            ld4(av[n], B2 + j0);
        }
    }

    // ---- epilogue: y for t = T-1 ----
    {
        float yv = hsum2(py2);
        yv += __shfl_xor_sync(0xffffffffu, yv, 1);
        yv += __shfl_xor_sync(0xffffffffu, yv, 2);
        yv += __shfl_xor_sync(0xffffffffu, yv, 4);
        if (q == 0) yPtr[(size_t)(T - 1) * STEP] = yv;
    }

    // ---- final state ----
    {
        float* op = sOut + ((size_t)h * NN + i) * NN + j0;
        ulonglong2 lo, hi;
        lo.x = s2[0]; lo.y = s2[1];
        hi.x = s2[2]; hi.y = s2[3];
        *reinterpret_cast<ulonglong2*>(op)     = lo;
        *reinterpret_cast<ulonglong2*>(op + 4) = hi;
    }
}

extern "C" void kernel_launch(void* const* d_in, const int* in_sizes, int n_in,
                              void* d_out, int out_size)
{
    const float* r  = (const float*)d_in[0];
    const float* w  = (const float*)d_in[1];
    const float* k  = (const float*)d_in[2];
    const float* v  = (const float*)d_in[3];
    const float* a  = (const float*)d_in[4];
    const float* b  = (const float*)d_in[5];
    const float* st = (const float*)d_in[6];

    const int T = in_sizes[0] / (HH * NN);

    float* y    = (float*)d_out;
    float* sfin = y + (size_t)T * HH * NN;

    wkv7_scan_kernel<<<HH * 16, 32>>>(r, w, k, v, a, b, st, y, sfin, T);
}